// round 2
// baseline (speedup 1.0000x reference)
#include <cuda_runtime.h>
#include <math.h>

#define NN 50000
#define EE 600000
#define DD 128
#define GG 8

// ---------------- scratch (device globals: no allocation allowed) ----------------
__device__ float d_agg[NN * DD];      // neighbor sums
__device__ float d_f[NN * DD];        // post-GELU features
__device__ int   d_deg[NN];
__device__ float d_invdeg[NN];
__device__ float d_gsum[GG * DD];
__device__ float d_gsumsq[GG * DD];
__device__ int   d_cnt[GG];
__device__ float d_An[GG * DD];       // scale  per (graph, dim)
__device__ float d_Bn[GG * DD];       // offset per (graph, dim)

// ---------------- zero scratch (must run every launch: graph replay) ----------------
__global__ void k_zero(int n) {
    int i = blockIdx.x * blockDim.x + threadIdx.x;
    int tot4 = n * (DD / 4);
    if (i < tot4) ((float4*)d_agg)[i] = make_float4(0.f, 0.f, 0.f, 0.f);
    if (i < n) d_deg[i] = 0;
    if (i < GG * DD) { d_gsum[i] = 0.f; d_gsumsq[i] = 0.f; }
    if (i < GG) d_cnt[i] = 0;
}

// ---------------- edge scatter: warp per edge, red.v4 into agg ----------------
__global__ void k_scatter(const float* __restrict__ x, const int* __restrict__ ei, int nE) {
    int w = (blockIdx.x * blockDim.x + threadIdx.x) >> 5;
    int lane = threadIdx.x & 31;
    if (w >= nE) return;
    int s = ei[w];
    int d = ei[nE + w];
    float4 v = ((const float4*)x)[(size_t)s * 32 + lane];
    float* p = &d_agg[(size_t)d * DD + lane * 4];
    asm volatile("red.global.add.v4.f32 [%0], {%1,%2,%3,%4};"
                 :: "l"(p), "f"(v.x), "f"(v.y), "f"(v.z), "f"(v.w) : "memory");
    if (lane == 0) atomicAdd(&d_deg[d], 1);
}

// ---------------- per-node: inv degree + warp-aggregated graph node counts ----------------
__global__ void k_node(const int* __restrict__ batch, int n) {
    int i = blockIdx.x * blockDim.x + threadIdx.x;
    bool valid = i < n;
    if (valid) d_invdeg[i] = 1.0f / fmaxf((float)d_deg[i], 1.0f);
    int key = valid ? batch[i] : -1;
    unsigned m = __match_any_sync(0xffffffffu, key);
    int leader = __ffs(m) - 1;
    if ((int)(threadIdx.x & 31) == leader && key >= 0)
        atomicAdd(&d_cnt[key], __popc(m));
}

// ---------------- fused dual-GEMM + bias + GELU + per-graph stat accumulation ----------------
// f[n][d] = gelu( sum_k aggn[n][k]*Wl[d][k] + x[n][k]*Wr[d][k] + bl[d] )
// BM=64 nodes per block, all 128 dims. blockDim=256; thread = (tx 0..15 dims, ty 0..15 nodes).
// Each thread: 4 nodes (ty*4+i), 8 dims (tx*4+j and 64+tx*4+j).
#define BM 64
__global__ __launch_bounds__(256) void k_gemm(
    const float* __restrict__ x,
    const float* __restrict__ Wl, const float* __restrict__ bl,
    const float* __restrict__ Wr,
    const int* __restrict__ batch, int n)
{
    __shared__ float As[BM][33];
    __shared__ float Ws[32][132];
    __shared__ float red[16][128];
    __shared__ int   bsm[BM];

    int t  = threadIdx.x;
    int n0 = blockIdx.x * BM;
    int tx = t & 15, ty = t >> 4;

    float acc[4][8];
#pragma unroll
    for (int i = 0; i < 4; ++i)
#pragma unroll
        for (int j = 0; j < 8; ++j) acc[i][j] = 0.f;

    if (t < BM) bsm[t] = (n0 + t < n) ? batch[n0 + t] : -1;

    for (int kc = 0; kc < 8; ++kc) {
        bool isAgg = kc < 4;
        int k0 = (kc & 3) * 32;
        const float* Wsrc = isAgg ? Wl : Wr;

        // load W chunk, transposed: Ws[kk][d] = W[d][k0+kk]
        {
            int kk = t & 31;
            int db = t >> 5; // 0..7
#pragma unroll
            for (int r = 0; r < 16; ++r) {
                int d = db + r * 8;
                Ws[kk][d] = Wsrc[(size_t)d * DD + k0 + kk];
            }
        }
        // load A chunk: As[node][kk]
        {
            int kk = t & 31;
            int rb = t >> 5; // 0..7
#pragma unroll
            for (int r = 0; r < 8; ++r) {
                int node = rb + r * 8;
                int gn = n0 + node;
                float v = 0.f;
                if (gn < n) {
                    if (isAgg) v = d_agg[(size_t)gn * DD + k0 + kk] * d_invdeg[gn];
                    else       v = x[(size_t)gn * DD + k0 + kk];
                }
                As[node][kk] = v;
            }
        }
        __syncthreads();

#pragma unroll
        for (int kk = 0; kk < 32; ++kk) {
            float a0 = As[ty * 4 + 0][kk];
            float a1 = As[ty * 4 + 1][kk];
            float a2 = As[ty * 4 + 2][kk];
            float a3 = As[ty * 4 + 3][kk];
            float4 w0 = *(const float4*)&Ws[kk][tx * 4];
            float4 w1 = *(const float4*)&Ws[kk][64 + tx * 4];
            acc[0][0] += a0 * w0.x; acc[0][1] += a0 * w0.y; acc[0][2] += a0 * w0.z; acc[0][3] += a0 * w0.w;
            acc[0][4] += a0 * w1.x; acc[0][5] += a0 * w1.y; acc[0][6] += a0 * w1.z; acc[0][7] += a0 * w1.w;
            acc[1][0] += a1 * w0.x; acc[1][1] += a1 * w0.y; acc[1][2] += a1 * w0.z; acc[1][3] += a1 * w0.w;
            acc[1][4] += a1 * w1.x; acc[1][5] += a1 * w1.y; acc[1][6] += a1 * w1.z; acc[1][7] += a1 * w1.w;
            acc[2][0] += a2 * w0.x; acc[2][1] += a2 * w0.y; acc[2][2] += a2 * w0.z; acc[2][3] += a2 * w0.w;
            acc[2][4] += a2 * w1.x; acc[2][5] += a2 * w1.y; acc[2][6] += a2 * w1.z; acc[2][7] += a2 * w1.w;
            acc[3][0] += a3 * w0.x; acc[3][1] += a3 * w0.y; acc[3][2] += a3 * w0.z; acc[3][3] += a3 * w0.w;
            acc[3][4] += a3 * w1.x; acc[3][5] += a3 * w1.y; acc[3][6] += a3 * w1.z; acc[3][7] += a3 * w1.w;
        }
        __syncthreads();
    }

    // bias + exact GELU
    int dlo = tx * 4;
    float bv[8];
#pragma unroll
    for (int j = 0; j < 4; ++j) { bv[j] = bl[dlo + j]; bv[4 + j] = bl[64 + dlo + j]; }
#pragma unroll
    for (int i = 0; i < 4; ++i)
#pragma unroll
        for (int j = 0; j < 8; ++j) {
            float v = acc[i][j] + bv[j];
            acc[i][j] = 0.5f * v * (1.0f + erff(v * 0.70710678118654752f));
        }

    // write f
#pragma unroll
    for (int i = 0; i < 4; ++i) {
        int gn = n0 + ty * 4 + i;
        if (gn < n) {
            float4 o0 = make_float4(acc[i][0], acc[i][1], acc[i][2], acc[i][3]);
            float4 o1 = make_float4(acc[i][4], acc[i][5], acc[i][6], acc[i][7]);
            ((float4*)d_f)[(size_t)gn * 32 + tx]      = o0;
            ((float4*)d_f)[(size_t)gn * 32 + 16 + tx] = o1;
        }
    }

    // per-graph sum / sumsq (batch sorted -> few graphs per block)
    int glo = bsm[0];
    int last = min(BM - 1, n - 1 - n0);
    int ghi = bsm[last];
    for (int g = glo; g <= ghi; ++g) {
        float s[8];
#pragma unroll
        for (int j = 0; j < 8; ++j) s[j] = 0.f;
#pragma unroll
        for (int i = 0; i < 4; ++i)
            if (bsm[ty * 4 + i] == g)
#pragma unroll
                for (int j = 0; j < 8; ++j) s[j] += acc[i][j];
#pragma unroll
        for (int j = 0; j < 4; ++j) { red[ty][dlo + j] = s[j]; red[ty][64 + dlo + j] = s[4 + j]; }
        __syncthreads();
        if (t < 128) {
            float tot = 0.f;
#pragma unroll
            for (int r = 0; r < 16; ++r) tot += red[r][t];
            atomicAdd(&d_gsum[g * DD + t], tot);
        }
        __syncthreads();
#pragma unroll
        for (int j = 0; j < 8; ++j) s[j] = 0.f;
#pragma unroll
        for (int i = 0; i < 4; ++i)
            if (bsm[ty * 4 + i] == g)
#pragma unroll
                for (int j = 0; j < 8; ++j) s[j] += acc[i][j] * acc[i][j];
#pragma unroll
        for (int j = 0; j < 4; ++j) { red[ty][dlo + j] = s[j]; red[ty][64 + dlo + j] = s[4 + j]; }
        __syncthreads();
        if (t < 128) {
            float tot = 0.f;
#pragma unroll
            for (int r = 0; r < 16; ++r) tot += red[r][t];
            atomicAdd(&d_gsumsq[g * DD + t], tot);
        }
        __syncthreads();
    }
}

// ---------------- per-(graph,dim) norm params ----------------
// var = E[f^2] - ms*(2-ms)*mean^2   (since out_pre = f - ms*mean)
__global__ void k_params(const float* __restrict__ gw, const float* __restrict__ gb,
                         const float* __restrict__ ms) {
    int i = blockIdx.x * blockDim.x + threadIdx.x;
    if (i >= GG * DD) return;
    int g = i >> 7, d = i & 127;
    float c = fmaxf((float)d_cnt[g], 1.f);
    float mean = d_gsum[i] / c;
    float m2 = d_gsumsq[i] / c;
    float m = ms[d];
    float var = m2 - m * (2.f - m) * mean * mean;
    var = fmaxf(var, 0.f);
    float rstd = rsqrtf(var + 1e-5f);
    float A = gw[d] * rstd;
    d_An[i] = A;
    d_Bn[i] = gb[d] - m * mean * A;
}

// ---------------- final: normalize + residual ----------------
__global__ void k_final(const float* __restrict__ x, const int* __restrict__ batch,
                        float* __restrict__ out, int n) {
    int i = blockIdx.x * blockDim.x + threadIdx.x;
    if (i >= n * 32) return;
    int node = i >> 5, c = i & 31;
    int g = batch[node];
    float4 f = ((const float4*)d_f)[i];
    float4 xv = ((const float4*)x)[i];
    float4 a = ((const float4*)d_An)[g * 32 + c];
    float4 b = ((const float4*)d_Bn)[g * 32 + c];
    float4 o;
    o.x = f.x * a.x + b.x + xv.x;
    o.y = f.y * a.y + b.y + xv.y;
    o.z = f.z * a.z + b.z + xv.z;
    o.w = f.w * a.w + b.w + xv.w;
    ((float4*)out)[i] = o;
}

// ---------------- launch ----------------
extern "C" void kernel_launch(void* const* d_in, const int* in_sizes, int n_in,
                              void* d_out, int out_size) {
    const float* x     = (const float*)d_in[0];
    const int*   ei    = (const int*)d_in[1];
    const int*   batch = (const int*)d_in[2];
    // d_in[3] = num_graphs scalar (GG fixed at compile time)
    const float* Wl  = (const float*)d_in[4];
    const float* bl  = (const float*)d_in[5];
    const float* Wr  = (const float*)d_in[6];
    const float* gw  = (const float*)d_in[7];
    const float* gb  = (const float*)d_in[8];
    const float* msc = (const float*)d_in[9];
    float* out = (float*)d_out;

    int n = in_sizes[0] / DD;
    int e = in_sizes[1] / 2;

    int tot4 = n * (DD / 4);
    k_zero<<<(tot4 + 255) / 256, 256>>>(n);
    k_scatter<<<((e * 32) + 255) / 256, 256>>>(x, ei, e);
    k_node<<<(n + 255) / 256, 256>>>(batch, n);
    k_gemm<<<(n + BM - 1) / BM, 256>>>(x, Wl, bl, Wr, batch, n);
    k_params<<<4, 256>>>(gw, gb, msc);
    k_final<<<(n * 32 + 255) / 256, 256>>>(x, batch, out, n);
}

// round 5
// speedup vs baseline: 1.1646x; 1.1646x over previous
#include <cuda_runtime.h>
#include <cuda_bf16.h>
#include <math.h>

#define NN 50000
#define EE 600000
#define DD 128
#define GG 8

// ---------------- scratch (device globals: no allocation allowed) ----------------
__device__ float d_agg[NN * DD];
__device__ float d_f[NN * DD];
__device__ int   d_deg[NN];
__device__ float d_invdeg[NN];
__device__ float d_gsum[GG * DD];
__device__ float d_gsumsq[GG * DD];
__device__ int   d_cnt[GG];
__device__ float d_An[GG * DD];
__device__ float d_Bn[GG * DD];

// ---------------- zero scratch ----------------
__global__ void k_zero(int n) {
    int i = blockIdx.x * blockDim.x + threadIdx.x;
    int tot4 = n * (DD / 4);
    if (i < tot4) ((float4*)d_agg)[i] = make_float4(0.f, 0.f, 0.f, 0.f);
    if (i < n) d_deg[i] = 0;
    if (i < GG * DD) { d_gsum[i] = 0.f; d_gsumsq[i] = 0.f; }
    if (i < GG) d_cnt[i] = 0;
}

// ---------------- edge scatter: warp per edge, red.v4 ----------------
__global__ void k_scatter(const float* __restrict__ x, const int* __restrict__ ei, int nE) {
    int w = (blockIdx.x * blockDim.x + threadIdx.x) >> 5;
    int lane = threadIdx.x & 31;
    if (w >= nE) return;
    int s = ei[w];
    int d = ei[nE + w];
    float4 v = ((const float4*)x)[(size_t)s * 32 + lane];
    float* p = &d_agg[(size_t)d * DD + lane * 4];
    asm volatile("red.global.add.v4.f32 [%0], {%1,%2,%3,%4};"
                 :: "l"(p), "f"(v.x), "f"(v.y), "f"(v.z), "f"(v.w) : "memory");
    if (lane == 0) atomicAdd(&d_deg[d], 1);
}

// ---------------- per-node invdeg + graph counts ----------------
__global__ void k_node(const int* __restrict__ batch, int n) {
    int i = blockIdx.x * blockDim.x + threadIdx.x;
    bool valid = i < n;
    if (valid) d_invdeg[i] = 1.0f / fmaxf((float)d_deg[i], 1.0f);
    int key = valid ? batch[i] : -1;
    unsigned m = __match_any_sync(0xffffffffu, key);
    int leader = __ffs(m) - 1;
    if ((int)(threadIdx.x & 31) == leader && key >= 0)
        atomicAdd(&d_cnt[key], __popc(m));
}

// ---------------- tensor-core dual GEMM + GELU + stats ----------------
// f[n][d] = gelu( agg_n[n][:]@Wl[d][:] + x[n][:]@Wr[d][:] + bl[d] )
// bf16 split-precision (hi/lo), mma.sync.m16n8k16, 128 nodes x 128 dims / block.
#define BM 128
#define STR 20   // smem row stride in u32 (16 pairs + pad 4: bank-conflict-free)

#define MMA_B16(c, a, b0v, b1v)                                            \
    asm volatile(                                                          \
        "mma.sync.aligned.m16n8k16.row.col.f32.bf16.bf16.f32 "             \
        "{%0,%1,%2,%3},{%4,%5,%6,%7},{%8,%9},{%0,%1,%2,%3};\n"             \
        : "+f"(c[0]), "+f"(c[1]), "+f"(c[2]), "+f"(c[3])                   \
        : "r"(a[0]), "r"(a[1]), "r"(a[2]), "r"(a[3]), "r"(b0v), "r"(b1v))

__device__ __forceinline__ void split2(float2 v, unsigned& h, unsigned& l) {
    __nv_bfloat16 hx = __float2bfloat16_rn(v.x);
    __nv_bfloat16 hy = __float2bfloat16_rn(v.y);
    __nv_bfloat16 lx = __float2bfloat16_rn(v.x - __bfloat162float(hx));
    __nv_bfloat16 ly = __float2bfloat16_rn(v.y - __bfloat162float(hy));
    h = ((unsigned)__bfloat16_as_ushort(hy) << 16) | __bfloat16_as_ushort(hx);
    l = ((unsigned)__bfloat16_as_ushort(ly) << 16) | __bfloat16_as_ushort(lx);
}

__global__ __launch_bounds__(256, 2) void k_gemm(
    const float* __restrict__ x,
    const float* __restrict__ Wl, const float* __restrict__ bl,
    const float* __restrict__ Wr,
    const int* __restrict__ batch, int n)
{
    __shared__ unsigned As_h[BM * STR], As_l[BM * STR];
    __shared__ unsigned Bs_h[DD * STR], Bs_l[DD * STR];
    __shared__ float red_s[8][66], red_q[8][66];
    __shared__ int   bsm[BM];
    __shared__ float inv_s[BM], bias_s[DD];

    int t = threadIdx.x;
    int n0 = blockIdx.x * BM;
    int wid = t >> 5, lane = t & 31;
    int wm = wid >> 1, wn = wid & 1;   // 4 x 2 warp grid: 32 rows x 64 cols per warp
    int r = lane >> 2, q4 = lane & 3;

    if (t < BM) {
        int gn = n0 + t;
        bsm[t]   = (gn < n) ? batch[gn] : -1;
        inv_s[t] = (gn < n) ? d_invdeg[gn] : 0.f;
        bias_s[t] = bl[t];
    }

    float acc[2][8][4];
#pragma unroll
    for (int mt = 0; mt < 2; ++mt)
#pragma unroll
        for (int nt = 0; nt < 8; ++nt)
#pragma unroll
            for (int j = 0; j < 4; ++j) acc[mt][nt][j] = 0.f;

    for (int kc = 0; kc < 8; ++kc) {
        bool isAgg = kc < 4;
        int k0 = (kc & 3) * 32;
        const float* Asrc = isAgg ? d_agg : x;
        const float* Wsrc = isAgg ? Wl : Wr;
        __syncthreads();
#pragma unroll
        for (int rr = 0; rr < 8; ++rr) {
            int idx = t + rr * 256;        // 0..2047
            int row = idx >> 4, pr = idx & 15;
            // A (node row)
            float2 v = make_float2(0.f, 0.f);
            int gn = n0 + row;
            if (gn < n) v = *(const float2*)(Asrc + (size_t)gn * DD + k0 + pr * 2);
            if (isAgg) { float sc = inv_s[row]; v.x *= sc; v.y *= sc; }
            unsigned h, l;
            split2(v, h, l);
            As_h[row * STR + pr] = h; As_l[row * STR + pr] = l;
            // B (dim row)
            float2 w = *(const float2*)(Wsrc + (size_t)row * DD + k0 + pr * 2);
            split2(w, h, l);
            Bs_h[row * STR + pr] = h; Bs_l[row * STR + pr] = l;
        }
        __syncthreads();

#pragma unroll
        for (int st = 0; st < 2; ++st) {
            int pb = st * 8 + q4;
            unsigned ah[2][4], al[2][4];
#pragma unroll
            for (int mt = 0; mt < 2; ++mt) {
                int row = wm * 32 + mt * 16 + r;
                ah[mt][0] = As_h[row * STR + pb];
                ah[mt][1] = As_h[(row + 8) * STR + pb];
                ah[mt][2] = As_h[row * STR + pb + 4];
                ah[mt][3] = As_h[(row + 8) * STR + pb + 4];
                al[mt][0] = As_l[row * STR + pb];
                al[mt][1] = As_l[(row + 8) * STR + pb];
                al[mt][2] = As_l[row * STR + pb + 4];
                al[mt][3] = As_l[(row + 8) * STR + pb + 4];
            }
#pragma unroll
            for (int nt = 0; nt < 8; ++nt) {
                int nr = wn * 64 + nt * 8 + r;
                unsigned bh0 = Bs_h[nr * STR + pb], bh1 = Bs_h[nr * STR + pb + 4];
                unsigned bl0 = Bs_l[nr * STR + pb], bl1 = Bs_l[nr * STR + pb + 4];
#pragma unroll
                for (int mt = 0; mt < 2; ++mt) {
                    MMA_B16(acc[mt][nt], ah[mt], bh0, bh1);
                    MMA_B16(acc[mt][nt], ah[mt], bl0, bl1);
                    MMA_B16(acc[mt][nt], al[mt], bh0, bh1);
                }
            }
        }
    }

    // bias + exact GELU
#pragma unroll
    for (int mt = 0; mt < 2; ++mt)
#pragma unroll
        for (int nt = 0; nt < 8; ++nt) {
            int d0 = wn * 64 + nt * 8 + q4 * 2;
            float b0v = bias_s[d0], b1v = bias_s[d0 + 1];
            float* c = acc[mt][nt];
            c[0] += b0v; c[1] += b1v; c[2] += b0v; c[3] += b1v;
#pragma unroll
            for (int j = 0; j < 4; ++j) {
                float v = c[j];
                c[j] = 0.5f * v * (1.0f + erff(v * 0.70710678118654752f));
            }
        }

    // write f
#pragma unroll
    for (int mt = 0; mt < 2; ++mt) {
        int nl0 = wm * 32 + mt * 16 + r;
#pragma unroll
        for (int rr = 0; rr < 2; ++rr) {
            int node = n0 + nl0 + rr * 8;
            if (node < n) {
#pragma unroll
                for (int nt = 0; nt < 8; ++nt) {
                    float2 o = make_float2(acc[mt][nt][rr * 2], acc[mt][nt][rr * 2 + 1]);
                    *(float2*)(d_f + (size_t)node * DD + wn * 64 + nt * 8 + q4 * 2) = o;
                }
            }
        }
    }

    // per-graph sum / sumsq
    int last = min(BM - 1, n - 1 - n0);
    int glo = bsm[0], ghi = bsm[last];
    for (int g = glo; g <= ghi; ++g) {
        float s[16];
#pragma unroll
        for (int i = 0; i < 16; ++i) s[i] = 0.f;
#pragma unroll
        for (int mt = 0; mt < 2; ++mt)
#pragma unroll
            for (int rr = 0; rr < 2; ++rr) {
                int nl = wm * 32 + mt * 16 + r + rr * 8;
                if (bsm[nl] == g)
#pragma unroll
                    for (int nt = 0; nt < 8; ++nt) {
                        s[nt * 2]     += acc[mt][nt][rr * 2];
                        s[nt * 2 + 1] += acc[mt][nt][rr * 2 + 1];
                    }
            }
#pragma unroll
        for (int off = 4; off < 32; off <<= 1)
#pragma unroll
            for (int i = 0; i < 16; ++i) s[i] += __shfl_xor_sync(0xffffffffu, s[i], off);
        if (lane < 4)
#pragma unroll
            for (int nt = 0; nt < 8; ++nt) {
                red_s[wid][nt * 8 + lane * 2]     = s[nt * 2];
                red_s[wid][nt * 8 + lane * 2 + 1] = s[nt * 2 + 1];
            }
        // squares
#pragma unroll
        for (int i = 0; i < 16; ++i) s[i] = 0.f;
#pragma unroll
        for (int mt = 0; mt < 2; ++mt)
#pragma unroll
            for (int rr = 0; rr < 2; ++rr) {
                int nl = wm * 32 + mt * 16 + r + rr * 8;
                if (bsm[nl] == g)
#pragma unroll
                    for (int nt = 0; nt < 8; ++nt) {
                        float v0 = acc[mt][nt][rr * 2], v1 = acc[mt][nt][rr * 2 + 1];
                        s[nt * 2]     += v0 * v0;
                        s[nt * 2 + 1] += v1 * v1;
                    }
            }
#pragma unroll
        for (int off = 4; off < 32; off <<= 1)
#pragma unroll
            for (int i = 0; i < 16; ++i) s[i] += __shfl_xor_sync(0xffffffffu, s[i], off);
        if (lane < 4)
#pragma unroll
            for (int nt = 0; nt < 8; ++nt) {
                red_q[wid][nt * 8 + lane * 2]     = s[nt * 2];
                red_q[wid][nt * 8 + lane * 2 + 1] = s[nt * 2 + 1];
            }
        __syncthreads();
        if (t < 128) {
            int wn_ = t >> 6, dl = t & 63;
            float ts = 0.f, tq = 0.f;
#pragma unroll
            for (int wm_ = 0; wm_ < 4; ++wm_) {
                ts += red_s[wm_ * 2 + wn_][dl];
                tq += red_q[wm_ * 2 + wn_][dl];
            }
            atomicAdd(&d_gsum[g * DD + t], ts);
            atomicAdd(&d_gsumsq[g * DD + t], tq);
        }
        __syncthreads();
    }
}

// ---------------- per-(graph,dim) norm params ----------------
__global__ void k_params(const float* __restrict__ gw, const float* __restrict__ gb,
                         const float* __restrict__ ms) {
    int i = blockIdx.x * blockDim.x + threadIdx.x;
    if (i >= GG * DD) return;
    int g = i >> 7, d = i & 127;
    float c = fmaxf((float)d_cnt[g], 1.f);
    float mean = d_gsum[i] / c;
    float m2 = d_gsumsq[i] / c;
    float m = ms[d];
    float var = m2 - m * (2.f - m) * mean * mean;
    var = fmaxf(var, 0.f);
    float rstd = rsqrtf(var + 1e-5f);
    float A = gw[d] * rstd;
    d_An[i] = A;
    d_Bn[i] = gb[d] - m * mean * A;
}

// ---------------- final: normalize + residual ----------------
__global__ void k_final(const float* __restrict__ x, const int* __restrict__ batch,
                        float* __restrict__ out, int n) {
    int i = blockIdx.x * blockDim.x + threadIdx.x;
    if (i >= n * 32) return;
    int node = i >> 5, c = i & 31;
    int g = batch[node];
    float4 f = ((const float4*)d_f)[i];
    float4 xv = ((const float4*)x)[i];
    float4 a = ((const float4*)d_An)[g * 32 + c];
    float4 b = ((const float4*)d_Bn)[g * 32 + c];
    float4 o;
    o.x = f.x * a.x + b.x + xv.x;
    o.y = f.y * a.y + b.y + xv.y;
    o.z = f.z * a.z + b.z + xv.z;
    o.w = f.w * a.w + b.w + xv.w;
    ((float4*)out)[i] = o;
}

// ---------------- launch ----------------
extern "C" void kernel_launch(void* const* d_in, const int* in_sizes, int n_in,
                              void* d_out, int out_size) {
    const float* x     = (const float*)d_in[0];
    const int*   ei    = (const int*)d_in[1];
    const int*   batch = (const int*)d_in[2];
    const float* Wl  = (const float*)d_in[4];
    const float* bl  = (const float*)d_in[5];
    const float* Wr  = (const float*)d_in[6];
    const float* gw  = (const float*)d_in[7];
    const float* gb  = (const float*)d_in[8];
    const float* msc = (const float*)d_in[9];
    float* out = (float*)d_out;

    int n = in_sizes[0] / DD;
    int e = in_sizes[1] / 2;

    int tot4 = n * (DD / 4);
    k_zero<<<(tot4 + 255) / 256, 256>>>(n);
    k_scatter<<<((e * 32) + 255) / 256, 256>>>(x, ei, e);
    k_node<<<(n + 255) / 256, 256>>>(batch, n);
    k_gemm<<<(n + BM - 1) / BM, 256>>>(x, Wl, bl, Wr, batch, n);
    k_params<<<4, 256>>>(gw, gb, msc);
    k_final<<<(n * 32 + 255) / 256, 256>>>(x, batch, out, n);
}